// round 11
// baseline (speedup 1.0000x reference)
#include <cuda_runtime.h>
#include <cstdint>

#define TT 2048
#define BB 512
#define KK 8
#define DD 32
#define DT_F 0.05f
#define SQDT_F 0.22360679774997896f  /* sqrt(0.05) */

// Normalized weights: float4 halves (w0..w3)(w4..w7) at ((t*BB+b)*2 + kh).
__device__ float g_wn[(size_t)TT * BB * KK];

// ---------- f32x2 helpers ----------
__device__ __forceinline__ unsigned long long add2(unsigned long long a, unsigned long long b) {
    unsigned long long d;
    asm("add.rn.f32x2 %0, %1, %2;" : "=l"(d) : "l"(a), "l"(b));
    return d;
}
__device__ __forceinline__ void ffma2(unsigned long long& d, unsigned long long a, unsigned long long b) {
    asm("fma.rn.f32x2 %0, %1, %2, %3;" : "=l"(d) : "l"(a), "l"(b), "l"(d));
}
__device__ __forceinline__ unsigned long long pack2(float lo, float hi) {
    unsigned long long v;
    asm("mov.b64 %0, {%1, %2};" : "=l"(v) : "f"(lo), "f"(hi));
    return v;
}
__device__ __forceinline__ void unpack2(unsigned long long v, float& lo, float& hi) {
    asm("mov.b64 {%0, %1}, %2;" : "=f"(lo), "=f"(hi) : "l"(v));
}

// ---------- Kernel 1: normalized weights ----------
__global__ void __launch_bounds__(256) norm_kernel(const float* __restrict__ s_probs) {
    int idx = blockIdx.x * blockDim.x + threadIdx.x;
    if (idx < TT * BB) {
        const float4* p = (const float4*)(s_probs + (size_t)idx * KK);
        float4 a = p[0];
        float4 b = p[1];
        float s = ((a.x + a.y) + (a.z + a.w)) + ((b.x + b.y) + (b.z + b.w));
        float r = 1.0f / s;
        float4* o = (float4*)(g_wn + (size_t)idx * KK);
        o[0] = make_float4(a.x * r, a.y * r, a.z * r, a.w * r);
        o[1] = make_float4(b.x * r, b.y * r, b.z * r, b.w * r);
    }
}

// Matvec + f32x2 weighted epilogue for one batch with this warp's 4 matrices.
// Returns d = sum_k w_k*(A_k z)[lane] + sum_k w_k b_k[lane], q = sum_k w_k Q_k[lane].
__device__ __forceinline__ void matvec_half(
    const float* __restrict__ zsm,
    const unsigned long long (&A)[4][16],
    const unsigned long long (&Q2)[4],
    float4 w4, float& d, float& q)
{
    unsigned long long ca0 = 0ull, ca1 = 0ull, ca2 = 0ull, ca3 = 0ull;
    unsigned long long cb0 = 0ull, cb1 = 0ull, cb2 = 0ull, cb3 = 0ull;
    const ulonglong2* zv = (const ulonglong2*)zsm;
#pragma unroll
    for (int jj = 0; jj < 8; jj++) {
        ulonglong2 z2 = zv[jj];                 // LDS.128 broadcast
        ffma2(ca0, A[0][2 * jj], z2.x);  ffma2(cb0, A[0][2 * jj + 1], z2.y);
        ffma2(ca1, A[1][2 * jj], z2.x);  ffma2(cb1, A[1][2 * jj + 1], z2.y);
        ffma2(ca2, A[2][2 * jj], z2.x);  ffma2(cb2, A[2][2 * jj + 1], z2.y);
        ffma2(ca3, A[3][2 * jj], z2.x);  ffma2(cb3, A[3][2 * jj + 1], z2.y);
    }
    unsigned long long w20 = pack2(w4.x, w4.x);
    unsigned long long w21 = pack2(w4.y, w4.y);
    unsigned long long w22 = pack2(w4.z, w4.z);
    unsigned long long w23 = pack2(w4.w, w4.w);
    unsigned long long P = 0ull, T = 0ull;
    ffma2(P, w20, add2(ca0, cb0));  ffma2(T, w20, Q2[0]);
    ffma2(P, w21, add2(ca1, cb1));  ffma2(T, w21, Q2[1]);
    ffma2(P, w22, add2(ca2, cb2));  ffma2(T, w22, Q2[2]);
    ffma2(P, w23, add2(ca3, cb3));  ffma2(T, w23, Q2[3]);
    float plo, phi, bsum, qsum;
    unpack2(P, plo, phi);
    unpack2(T, bsum, qsum);
    d = (plo + phi) + bsum;
    q = qsum;
}

// ---------- Kernel 2: antiphase-pipelined, 4 batches per 128-thr CTA ----------
// Warp w: pr = w>>1 selects batch pair {bA,bB}; kh = w&1 selects matrices
// {4kh..4kh+3} (128 A regs). Per barrier interval each warp does the MATVEC
// for one batch and (one warp) the UPDATE for the other; all post-barrier
// inputs were produced before the previous barrier -> no dependency stalls.
// kh0 owns batch A's update/state, kh1 owns batch B's.
__global__ void __launch_bounds__(128, 1) sde_main(
    const float* __restrict__ z0,
    const float* __restrict__ noise,
    const float* __restrict__ A_s,
    const float* __restrict__ b_s,
    const float* __restrict__ Q_chol,
    float* __restrict__ ys)
{
    const int tid  = threadIdx.x;
    const int w    = tid >> 5;
    const int lane = tid & 31;       // row
    const int pr   = w >> 1;         // pair 0/1
    const int kh   = w & 1;          // k-half
    const int kb   = kh * 4;
    const int bA   = blockIdx.x * 4 + pr * 2;
    const int bB   = bA + 1;
    const int bO   = kh ? bB : bA;   // batch owned by this warp (update/state)

    __shared__ __align__(16) float  zA[2][DD], zB[2][DD];   // [pair][row]
    __shared__ __align__(16) float2 pA[2][DD], pB[2][DD];   // cross-half partials

    // ---- A rows (lane) of A_{kb..kb+3} -> 64 ull regs ----
    unsigned long long A[4][16];
    unsigned long long Q2[4];
#pragma unroll
    for (int kk = 0; kk < 4; kk++) {
        const ulonglong2* r = (const ulonglong2*)(A_s + (size_t)((kb + kk) * DD + lane) * DD);
#pragma unroll
        for (int p = 0; p < 8; p++) {
            ulonglong2 v = r[p];
            A[kk][2 * p]     = v.x;
            A[kk][2 * p + 1] = v.y;
        }
        Q2[kk] = pack2(b_s[(kb + kk) * DD + lane], Q_chol[(kb + kk) * DD + lane]);
    }

    // ---- state init ----
    float zreg = z0[(size_t)bO * DD + lane];   // owned batch's state (register copy)
    if (kh == 0) zA[pr][lane] = zreg;
    else         zB[pr][lane] = zreg;

    // streams: each warp loads w for BOTH batches (its k-half), dw for owned batch
    const float4* wnp = (const float4*)g_wn;   // index ((t*BB+b)*2 + kh)
    const float*  np  = noise + (size_t)bO * DD + lane;
    float*        yp  = ys    + (size_t)bO * DD + lane;

    float4 wA_n = __ldg(&wnp[((size_t)0 * BB + bA) * 2 + kh]);   // w_A(0) for prologue
    float4 wB_c = __ldg(&wnp[((size_t)0 * BB + bB) * 2 + kh]);   // w_B(0)
    float  dw_c = SQDT_F * __ldg(&np[0]);                        // dw_own(0)
    float4 wA_1 = __ldg(&wnp[((size_t)1 * BB + bA) * 2 + kh]);   // w_A(1)
    float4 wB_n = __ldg(&wnp[((size_t)1 * BB + bB) * 2 + kh]);   // w_B(1)
    float  dw_n = SQDT_F * __ldg(&np[(size_t)1 * (BB * DD)]);    // dw_own(1)

    __syncthreads();

    // ---- prologue: matvec A(0) ----
    float myAd, myAq, myBd = 0.0f, myBq = 0.0f;
    matvec_half(&zA[pr][0], A, Q2, wA_n, myAd, myAq);
    if (kh == 1) pA[pr][lane] = make_float2(myAd, myAq);
    wA_n = wA_1;
    __syncthreads();

    for (int t = 0; t < TT; t++) {
        // prefetch t+2 (clamped)
        int tp = t + 2; if (tp >= TT) tp = TT - 1;
        float4 wA_l = __ldg(&wnp[((size_t)tp * BB + bA) * 2 + kh]);
        float4 wB_l = __ldg(&wnp[((size_t)tp * BB + bB) * 2 + kh]);
        float  dw_l = SQDT_F * __ldg(&np[(size_t)tp * (BB * DD)]);

        // ---- block 2: matvec B(t); kh0 updates A(t) ----
        matvec_half(&zB[pr][0], A, Q2, wB_c, myBd, myBq);
        if (kh == 0) {
            pB[pr][lane] = make_float2(myBd, myBq);    // for kh1's updB below
            float2 o = pA[pr][lane];                    // kh1's A-partial (pre-bar)
            zreg = fmaf(DT_F, myAd + o.x, fmaf(dw_c, myAq + o.y, zreg));
            zA[pr][lane] = zreg;
            yp[(size_t)t * (BB * DD)] = zreg;           // ys_A[t]
        }
        __syncthreads();

        // ---- block 1': matvec A(t+1); kh1 updates B(t) ----
        matvec_half(&zA[pr][0], A, Q2, wA_n, myAd, myAq);
        if (kh == 1) {
            float2 o = pB[pr][lane];                    // kh0's B-partial (pre-bar)
            zreg = fmaf(DT_F, myBd + o.x, fmaf(dw_c, myBq + o.y, zreg));
            zB[pr][lane] = zreg;
            yp[(size_t)t * (BB * DD)] = zreg;           // ys_B[t]
            pA[pr][lane] = make_float2(myAd, myAq);     // for kh0's updA(t+1)
        }
        // rotate streams
        wA_n = wA_l;
        wB_c = wB_n;  wB_n = wB_l;
        dw_c = dw_n;  dw_n = dw_l;
        __syncthreads();
    }
}

extern "C" void kernel_launch(void* const* d_in, const int* in_sizes, int n_in,
                              void* d_out, int out_size) {
    const float* z0      = (const float*)d_in[0];
    const float* s_probs = (const float*)d_in[1];
    const float* noise   = (const float*)d_in[2];
    const float* A_s     = (const float*)d_in[3];
    const float* b_s     = (const float*)d_in[4];
    const float* Q_chol  = (const float*)d_in[5];
    float*       ys      = (float*)d_out;

    norm_kernel<<<(TT * BB + 255) / 256, 256>>>(s_probs);
    sde_main<<<BB / 4, 128>>>(z0, noise, A_s, b_s, Q_chol, ys);
}

// round 12
// speedup vs baseline: 1.3294x; 1.3294x over previous
#include <cuda_runtime.h>
#include <cstdint>

#define TT 2048
#define BB 512
#define KK 8
#define DD 32
#define DT_F 0.05f
#define SQDT_F 0.22360679774997896f  /* sqrt(0.05) */

// Static scratch (no allocs):
// g_w2:  dt-scaled normalized weights, 8 floats per (t,b): [dt*w0..dt*w7]
// g_add: addend[t,b,i] = dt*sum_k w_k b_k[i] + sqrt(dt)*noise[t,b,i]*sum_k w_k Q_k[i]
__device__ float g_w2[(size_t)TT * BB * KK];
__device__ float g_add[(size_t)TT * BB * DD];

// ---------- f32x2 helpers ----------
__device__ __forceinline__ unsigned long long add2(unsigned long long a, unsigned long long b) {
    unsigned long long d;
    asm("add.rn.f32x2 %0, %1, %2;" : "=l"(d) : "l"(a), "l"(b));
    return d;
}
__device__ __forceinline__ void ffma2(unsigned long long& d, unsigned long long a, unsigned long long b) {
    asm("fma.rn.f32x2 %0, %1, %2, %3;" : "=l"(d) : "l"(a), "l"(b), "l"(d));
}
__device__ __forceinline__ unsigned long long pack2(float lo, float hi) {
    unsigned long long v;
    asm("mov.b64 %0, {%1, %2};" : "=l"(v) : "f"(lo), "f"(hi));
    return v;
}
__device__ __forceinline__ void unpack2(unsigned long long v, float& lo, float& hi) {
    asm("mov.b64 {%0, %1}, %2;" : "=f"(lo), "=f"(hi) : "l"(v));
}

// ---------- Kernel 1: prep — normalize weights (dt-scaled) + fold b/Q/noise ----------
// Warp-per-pair loop; b_s/Q_chol rows live in REGISTERS (lane = i), so no
// redundant table traffic (R9's prep mistake). All streams coalesced.
__global__ void __launch_bounds__(256) prep_kernel(
    const float* __restrict__ s_probs,
    const float* __restrict__ noise,
    const float* __restrict__ b_s,
    const float* __restrict__ Q_chol)
{
    const int lane = threadIdx.x & 31;
    const int gw   = (blockIdx.x * 256 + threadIdx.x) >> 5;
    const int nw   = (gridDim.x * 256) >> 5;

    float bk[KK], qk[KK];
#pragma unroll
    for (int k = 0; k < KK; k++) {
        bk[k] = b_s[k * DD + lane];
        qk[k] = Q_chol[k * DD + lane];
    }

    for (size_t pair = gw; pair < (size_t)TT * BB; pair += nw) {
        const float4* sp = (const float4*)(s_probs + pair * KK);
        float4 a = __ldg(sp);
        float4 c = __ldg(sp + 1);
        float s = ((a.x + a.y) + (a.z + a.w)) + ((c.x + c.y) + (c.z + c.w));
        float r = 1.0f / s;
        float w0 = a.x * r, w1 = a.y * r, w2 = a.z * r, w3 = a.w * r;
        float w4 = c.x * r, w5 = c.y * r, w6 = c.z * r, w7 = c.w * r;

        float bsum = w0 * bk[0];
        bsum = fmaf(w1, bk[1], bsum); bsum = fmaf(w2, bk[2], bsum);
        bsum = fmaf(w3, bk[3], bsum); bsum = fmaf(w4, bk[4], bsum);
        bsum = fmaf(w5, bk[5], bsum); bsum = fmaf(w6, bk[6], bsum);
        bsum = fmaf(w7, bk[7], bsum);
        float qsum = w0 * qk[0];
        qsum = fmaf(w1, qk[1], qsum); qsum = fmaf(w2, qk[2], qsum);
        qsum = fmaf(w3, qk[3], qsum); qsum = fmaf(w4, qk[4], qsum);
        qsum = fmaf(w5, qk[5], qsum); qsum = fmaf(w6, qk[6], qsum);
        qsum = fmaf(w7, qk[7], qsum);

        float nz = __ldg(noise + pair * DD + lane);
        g_add[pair * DD + lane] = fmaf(DT_F, bsum, (SQDT_F * nz) * qsum);

        if (lane == 0)
            ((float4*)g_w2)[pair * 2] =
                make_float4(DT_F * w0, DT_F * w1, DT_F * w2, DT_F * w3);
        if (lane == 1)
            ((float4*)g_w2)[pair * 2 + 1] =
                make_float4(DT_F * w4, DT_F * w5, DT_F * w6, DT_F * w7);
    }
}

// ---------- Kernel 2: COLUMN-split, one CTA (128 thr = 4 warps) per batch ----------
// Warp w owns columns 8w..8w+7 of ALL 8 matrices (lane = output row).
// Per step per warp: 2 LDS.128 (its 8 z cols, warp-private copy) + 32 FFMA2
// + 8 packed weight-combines + STS.32 partial + 1 __syncthreads + 4 LDS.32.
// Crossbar load per SM-step is ~2.3x lower than the k-split designs.
__global__ void __launch_bounds__(128, 4) sde_main(
    const float* __restrict__ z0,
    const float* __restrict__ A_s,
    float* __restrict__ ys)
{
    const int b    = blockIdx.x;
    const int tid  = threadIdx.x;
    const int w    = tid >> 5;        // column block 0..3
    const int lane = tid & 31;        // output row

    __shared__ __align__(16) float zown[4][DD];      // [warp][row] private z copies
    __shared__ __align__(16) float pbuf[2][4][DD];   // [parity][warp][row] col partials

    // ---- A: cols 8w..8w+7 of row `lane` for all 8 k -> 32 ull (64 regs) ----
    unsigned long long A[KK][4];
#pragma unroll
    for (int k = 0; k < KK; k++) {
        const ulonglong2* ap =
            (const ulonglong2*)(A_s + (size_t)k * DD * DD + lane * DD + 8 * w);
        ulonglong2 v0 = ap[0];
        ulonglong2 v1 = ap[1];
        A[k][0] = v0.x; A[k][1] = v0.y; A[k][2] = v1.x; A[k][3] = v1.y;
    }

    // ---- z init ----
    float zreg = z0[(size_t)b * DD + lane];
    zown[w][lane] = zreg;

    // stream pointers
    const float4* wp = (const float4*)g_w2;          // (t*BB+b)*2 + {0,1}
    const float*  ap = g_add + (size_t)b * DD + lane;
    float*        yp = ys    + (size_t)b * DD + lane;

    // ---- prefetch group 0 (UN = 2) ----
    float4 wa_c[2], wb_c[2]; float ad_c[2];
#pragma unroll
    for (int u = 0; u < 2; u++) {
        wa_c[u] = __ldg(&wp[((size_t)u * BB + b) * 2]);
        wb_c[u] = __ldg(&wp[((size_t)u * BB + b) * 2 + 1]);
        ad_c[u] = __ldg(&ap[(size_t)u * (BB * DD)]);
    }

    __syncthreads();

    for (int s0 = 0; s0 < TT; s0 += 2) {
        // ---- prefetch next group (clamped; tail values unused) ----
        float4 wa_n[2], wb_n[2]; float ad_n[2];
#pragma unroll
        for (int u = 0; u < 2; u++) {
            int ts = s0 + 2 + u;
            if (ts >= TT) ts = TT - 1;
            wa_n[u] = __ldg(&wp[((size_t)ts * BB + b) * 2]);
            wb_n[u] = __ldg(&wp[((size_t)ts * BB + b) * 2 + 1]);
            ad_n[u] = __ldg(&ap[(size_t)ts * (BB * DD)]);
        }

#pragma unroll
        for (int u = 0; u < 2; u++) {
            const int step = s0 + u;
            const int par  = step & 1;

            // ---- own z columns: 2 warp-uniform LDS.128 ----
            const ulonglong2* zv = (const ulonglong2*)(&zown[w][8 * w]);
            ulonglong2 zc01 = zv[0];
            ulonglong2 zc23 = zv[1];

            // ---- partial dots: 8 k x 4 FFMA2 (8 independent chains) ----
            unsigned long long acc[KK];
#pragma unroll
            for (int k = 0; k < KK; k++) {
                acc[k] = 0ull;
                ffma2(acc[k], A[k][0], zc01.x);
                ffma2(acc[k], A[k][1], zc01.y);
                ffma2(acc[k], A[k][2], zc23.x);
                ffma2(acc[k], A[k][3], zc23.y);
            }

            // ---- packed weighted k-combine (weights pre-scaled by dt) ----
            float4 wa = wa_c[u], wb = wb_c[u];
            unsigned long long P0 = 0ull, P1 = 0ull;
            ffma2(P0, pack2(wa.x, wa.x), acc[0]);
            ffma2(P1, pack2(wa.y, wa.y), acc[1]);
            ffma2(P0, pack2(wa.z, wa.z), acc[2]);
            ffma2(P1, pack2(wa.w, wa.w), acc[3]);
            ffma2(P0, pack2(wb.x, wb.x), acc[4]);
            ffma2(P1, pack2(wb.y, wb.y), acc[5]);
            ffma2(P0, pack2(wb.z, wb.z), acc[6]);
            ffma2(P1, pack2(wb.w, wb.w), acc[7]);
            float plo, phi;
            unpack2(add2(P0, P1), plo, phi);
            float pd = plo + phi;

            // ---- cross-warp column reduction: STS.32 + barrier + 4 LDS.32 ----
            pbuf[par][w][lane] = pd;
            __syncthreads();
            float sum = (pbuf[par][0][lane] + pbuf[par][1][lane])
                      + (pbuf[par][2][lane] + pbuf[par][3][lane]);

            // ---- z update (all warps redundantly; each owns its z copy) ----
            zreg += sum + ad_c[u];
            zown[w][lane] = zreg;
            __syncwarp();
            if (w == 0) yp[(size_t)step * (BB * DD)] = zreg;  // coalesced 128B
        }

        // rotate prefetch buffers
#pragma unroll
        for (int u = 0; u < 2; u++) {
            wa_c[u] = wa_n[u];
            wb_c[u] = wb_n[u];
            ad_c[u] = ad_n[u];
        }
    }
}

extern "C" void kernel_launch(void* const* d_in, const int* in_sizes, int n_in,
                              void* d_out, int out_size) {
    const float* z0      = (const float*)d_in[0];
    const float* s_probs = (const float*)d_in[1];
    const float* noise   = (const float*)d_in[2];
    const float* A_s     = (const float*)d_in[3];
    const float* b_s     = (const float*)d_in[4];
    const float* Q_chol  = (const float*)d_in[5];
    float*       ys      = (float*)d_out;

    prep_kernel<<<2048, 256>>>(s_probs, noise, b_s, Q_chol);
    sde_main<<<BB, 128>>>(z0, A_s, ys);
}

// round 13
// speedup vs baseline: 2.1191x; 1.5941x over previous
#include <cuda_runtime.h>
#include <cstdint>

#define TT 2048
#define BB 512
#define KK 8
#define DD 32
#define DT_F 0.05f
#define SQDT_F 0.22360679774997896f  /* sqrt(0.05) */
#define UN 4                          /* prefetch group / unroll */

// Scratch: normalized weights wn[t][b][k] = s_probs / sum_k. Static (no allocs).
__device__ float g_wn[(size_t)TT * BB * KK];

// ---------- f32x2 helpers (FFMA2 is PTX-only on sm_103a) ----------
__device__ __forceinline__ unsigned long long add2(unsigned long long a, unsigned long long b) {
    unsigned long long d;
    asm("add.rn.f32x2 %0, %1, %2;" : "=l"(d) : "l"(a), "l"(b));
    return d;
}
__device__ __forceinline__ void ffma2(unsigned long long& d, unsigned long long a, unsigned long long b) {
    asm("fma.rn.f32x2 %0, %1, %2, %3;" : "=l"(d) : "l"(a), "l"(b), "l"(d));
}
__device__ __forceinline__ unsigned long long pack2(float lo, float hi) {
    unsigned long long v;
    asm("mov.b64 %0, {%1, %2};" : "=l"(v) : "f"(lo), "f"(hi));
    return v;
}
__device__ __forceinline__ float hsum2(unsigned long long v) {
    float lo, hi;
    asm("mov.b64 {%0, %1}, %2;" : "=f"(lo), "=f"(hi) : "l"(v));
    return lo + hi;
}
__device__ __forceinline__ void unpack2(unsigned long long v, float& lo, float& hi) {
    asm("mov.b64 {%0, %1}, %2;" : "=f"(lo), "=f"(hi) : "l"(v));
}

// ---------- Kernel 1: normalized weights ----------
__global__ void __launch_bounds__(256) norm_kernel(const float* __restrict__ s_probs) {
    int idx = blockIdx.x * blockDim.x + threadIdx.x;  // (t,b) pair
    if (idx < TT * BB) {
        const float4* p = (const float4*)(s_probs + (size_t)idx * KK);
        float4 a = p[0];
        float4 b = p[1];
        float s = ((a.x + a.y) + (a.z + a.w)) + ((b.x + b.y) + (b.z + b.w));
        float r = 1.0f / s;
        float4* o = (float4*)(g_wn + (size_t)idx * KK);
        o[0] = make_float4(a.x * r, a.y * r, a.z * r, a.w * r);
        o[1] = make_float4(b.x * r, b.y * r, b.z * r, b.w * r);
    }
}

// ---------- Kernel 2: one CTA (64 thr = 2 warps) per batch (R4 shape) ----------
// Lane i of warp wp owns row i of A_{4wp+kk}, kk=0..3, PRE-SCALED BY dt at
// load time. Accumulators init with dt*b (bias folded). sqrt(dt) folded into
// qc. k-reduction over the warp's 4 k's is packed f32x2 register math;
// cross-warp reduction is one float2 smem exchange + 1 __syncthreads.
__global__ void __launch_bounds__(64, 4) sde_main(
    const float* __restrict__ z0,
    const float* __restrict__ noise,
    const float* __restrict__ A_s,
    const float* __restrict__ b_s,
    const float* __restrict__ Q_chol,
    float* __restrict__ ys)
{
    const int b    = blockIdx.x;
    const int tid  = threadIdx.x;
    const int w    = tid >> 5;       // 0 or 1
    const int lane = tid & 31;       // row i
    const int kb   = w * 4;          // k base

    __shared__ __align__(16) float  zbuf[2][DD];        // [warp][row] private z copies
    __shared__ __align__(16) float2 pbuf[2][2][DD];     // [parity][warp][row] partials

    // ---- A rows -> registers as f32x2 pairs, PRE-SCALED by dt ----
    unsigned long long A[4][16];
#pragma unroll
    for (int kk = 0; kk < 4; kk++) {
        const float4* r = (const float4*)(A_s + (size_t)((kb + kk) * DD + lane) * DD);
#pragma unroll
        for (int q = 0; q < 8; q++) {
            float4 v = r[q];
            A[kk][2 * q]     = pack2(DT_F * v.x, DT_F * v.y);
            A[kk][2 * q + 1] = pack2(DT_F * v.z, DT_F * v.w);
        }
    }
    unsigned long long binit[4];     // acc init: (dt*b_k, 0)
    float qc[4];                     // sqrt(dt)*Q_k
#pragma unroll
    for (int kk = 0; kk < 4; kk++) {
        binit[kk] = pack2(DT_F * b_s[(kb + kk) * DD + lane], 0.0f);
        qc[kk]    = SQDT_F * Q_chol[(kb + kk) * DD + lane];
    }

    // ---- z init ----
    float zreg = z0[(size_t)b * DD + lane];
    zbuf[w][lane] = zreg;

    // stream pointers
    const float4* wp4 = (const float4*)g_wn;            // idx = ((t*BB+b)*KK)/4 + w
    const float*  np  = noise + (size_t)b * DD + lane;  // + step*BB*DD
    float*        yp  = ys    + (size_t)b * DD + lane;

    // ---- prefetch group 0 ----
    float4 w4_c[UN]; float dw_c[UN];
#pragma unroll
    for (int u = 0; u < UN; u++) {
        w4_c[u] = __ldg(&wp4[((size_t)u * BB + b) * 2 + w]);
        dw_c[u] = __ldg(&np[(size_t)u * (BB * DD)]);    // raw noise (sqdt in qc)
    }

    __syncthreads();

    for (int s0 = 0; s0 < TT; s0 += UN) {
        // ---- prefetch next group (clamped; last-group values unused) ----
        float4 w4_n[UN]; float dw_n[UN];
#pragma unroll
        for (int u = 0; u < UN; u++) {
            int ts = s0 + UN + u;
            if (ts >= TT) ts = TT - 1;
            w4_n[u] = __ldg(&wp4[((size_t)ts * BB + b) * 2 + w]);
            dw_n[u] = __ldg(&np[(size_t)ts * (BB * DD)]);
        }

#pragma unroll
        for (int u = 0; u < UN; u++) {
            const int step = s0 + u;
            const int par  = step & 1;

            // ---- matvec: 4 rows vs z; acc pre-loaded with dt*b ----
            unsigned long long ca[4], cb[4];
#pragma unroll
            for (int kk = 0; kk < 4; kk++) { ca[kk] = binit[kk]; cb[kk] = 0ull; }
            const ulonglong2* zv = (const ulonglong2*)(&zbuf[w][0]);
#pragma unroll
            for (int jj = 0; jj < 8; jj++) {
                ulonglong2 z2 = zv[jj];                 // LDS.128 broadcast
#pragma unroll
                for (int kk = 0; kk < 4; kk++) {
                    ffma2(ca[kk], A[kk][2 * jj],     z2.x);
                    ffma2(cb[kk], A[kk][2 * jj + 1], z2.y);
                }
            }
            // a_k = dt*(A_k z + b_k)
            float a0 = hsum2(add2(ca[0], cb[0]));
            float a1 = hsum2(add2(ca[1], cb[1]));
            float a2 = hsum2(add2(ca[2], cb[2]));
            float a3 = hsum2(add2(ca[3], cb[3]));

            // ---- packed weighted combine: (pd, pq) in one f32x2 chain ----
            float4 wv = w4_c[u];
            unsigned long long P = 0ull;
            ffma2(P, pack2(wv.x, wv.x), pack2(a0, qc[0]));
            ffma2(P, pack2(wv.y, wv.y), pack2(a1, qc[1]));
            ffma2(P, pack2(wv.z, wv.z), pack2(a2, qc[2]));
            ffma2(P, pack2(wv.w, wv.w), pack2(a3, qc[3]));
            float pd, pq;
            unpack2(P, pd, pq);

            // ---- cross-warp reduction: one smem exchange + one barrier ----
            pbuf[par][w][lane] = make_float2(pd, pq);
            __syncthreads();
            float2 o = pbuf[par][w ^ 1][lane];

            // ---- z update (both warps redundantly; each owns its z copy) ----
            zreg = fmaf(pq + o.y, dw_c[u], zreg + (pd + o.x));
            zbuf[w][lane] = zreg;
            if (w == 0) yp[(size_t)step * (BB * DD)] = zreg;  // coalesced 128B
        }

        // rotate prefetch buffers
#pragma unroll
        for (int u = 0; u < UN; u++) {
            w4_c[u] = w4_n[u];
            dw_c[u] = dw_n[u];
        }
    }
}

extern "C" void kernel_launch(void* const* d_in, const int* in_sizes, int n_in,
                              void* d_out, int out_size) {
    const float* z0      = (const float*)d_in[0];
    const float* s_probs = (const float*)d_in[1];
    const float* noise   = (const float*)d_in[2];
    const float* A_s     = (const float*)d_in[3];
    const float* b_s     = (const float*)d_in[4];
    const float* Q_chol  = (const float*)d_in[5];
    float*       ys      = (float*)d_out;

    norm_kernel<<<(TT * BB + 255) / 256, 256>>>(s_probs);
    sde_main<<<BB, 64>>>(z0, noise, A_s, b_s, Q_chol, ys);
}